// round 3
// baseline (speedup 1.0000x reference)
#include <cuda_runtime.h>
#include <cstdint>

#define EPSF 1e-7f
#define MAX_NORM (1.0f - 1e-5f)
#define MAXN 100352   // capacity for N=100000

// Scratch (static device globals — no allocation allowed)
__device__ float g_h[(size_t)MAXN * 64];   // transformed node features
__device__ float g_deg[MAXN];              // in-degree accumulator
__device__ float g_W[64 * 64];             // expmap0(weight)
__device__ float g_B[64];                  // expmap0(bias)
__device__ float g_By2;                    // ||expmap0(bias)||^2 = tanh(||bias||)^2

// ---------------------------------------------------------------------------
// Kernel 0: tiny prep — expmap0 of weight rows and of bias
// ---------------------------------------------------------------------------
__global__ void prep_kernel(const float* __restrict__ weight,
                            const float* __restrict__ bias) {
    int i = threadIdx.x;
    if (i < 64) {
        float ss = 0.f;
        #pragma unroll
        for (int k = 0; k < 64; k++) { float w = weight[i * 64 + k]; ss += w * w; }
        float n = fmaxf(sqrtf(ss), EPSF);
        float s = tanhf(n) / n;
        #pragma unroll
        for (int k = 0; k < 64; k++) g_W[i * 64 + k] = weight[i * 64 + k] * s;
    }
    if (i == 0) {
        float ss = 0.f;
        #pragma unroll
        for (int k = 0; k < 64; k++) { float b = bias[k]; ss += b * b; }
        float n = fmaxf(sqrtf(ss), EPSF);
        float t = tanhf(n);
        float s = t / n;
        #pragma unroll
        for (int k = 0; k < 64; k++) g_B[k] = bias[k] * s;
        g_By2 = t * t;
    }
}

// ---------------------------------------------------------------------------
// Kernel 1: per-node hyperbolic transform
//   h = mobius_add(mobius_matvec(w_h, x), b_h)
// One thread per node. W in shared (broadcast LDS.128), x row via LDG.128.
// ---------------------------------------------------------------------------
__global__ void __launch_bounds__(256)
transform_kernel(const float* __restrict__ x, int N) {
    __shared__ float Ws[64 * 64];
    __shared__ float Bs[64];
    int tid = threadIdx.x;
    for (int i = tid; i < 64 * 64; i += 256) Ws[i] = g_W[i];
    if (tid < 64) Bs[tid] = g_B[tid];
    __syncthreads();

    int n = blockIdx.x * 256 + tid;
    if (n >= N) return;

    const float4* xrow = (const float4*)(x + (size_t)n * 64);

    float acc[64];
    #pragma unroll
    for (int d = 0; d < 64; d++) acc[d] = 0.f;

    float xn2 = 0.f;
    // k-loop: 16 iterations, 4 k's per iteration, inner d fully unrolled
    for (int k4 = 0; k4 < 16; k4++) {
        float4 xk4 = __ldg(xrow + k4);
        xn2 += xk4.x * xk4.x + xk4.y * xk4.y + xk4.z * xk4.z + xk4.w * xk4.w;
        float xk[4] = {xk4.x, xk4.y, xk4.z, xk4.w};
        #pragma unroll
        for (int kk = 0; kk < 4; kk++) {
            int k = k4 * 4 + kk;
            const float4* wrow = (const float4*)&Ws[k * 64];
            float xv = xk[kk];
            #pragma unroll
            for (int d4 = 0; d4 < 16; d4++) {
                float4 w = wrow[d4];
                acc[d4 * 4 + 0] = fmaf(xv, w.x, acc[d4 * 4 + 0]);
                acc[d4 * 4 + 1] = fmaf(xv, w.y, acc[d4 * 4 + 1]);
                acc[d4 * 4 + 2] = fmaf(xv, w.z, acc[d4 * 4 + 2]);
                acc[d4 * 4 + 3] = fmaf(xv, w.w, acc[d4 * 4 + 3]);
            }
        }
    }

    float xn = fmaxf(sqrtf(xn2), EPSF);
    float Mxn2 = 0.f;
    #pragma unroll
    for (int d = 0; d < 64; d++) Mxn2 += acc[d] * acc[d];
    float Mxn = fmaxf(sqrtf(Mxn2), EPSF);

    // artanh with reference clipping
    float xc = fminf(xn, 1.0f - 1e-7f);
    float at = 0.5f * log1pf(2.0f * xc / (1.0f - xc));
    float t  = tanhf(Mxn / xn * at);
    float scale = t / Mxn;

    // r = scale * Mx;  ||r|| = t exactly  =>  x2 = t^2
    float x2 = t * t;
    float xy = 0.f;
    #pragma unroll
    for (int d = 0; d < 64; d++) {
        acc[d] *= scale;
        xy = fmaf(acc[d], Bs[d], xy);
    }
    float y2  = g_By2;
    float ca  = 1.0f + 2.0f * xy + y2;
    float cb  = 1.0f - x2;
    float den = 1.0f + 2.0f * xy + x2 * y2;
    float inv = 1.0f / fmaxf(den, EPSF);

    float4* hrow = (float4*)(g_h + (size_t)n * 64);
    #pragma unroll
    for (int d4 = 0; d4 < 16; d4++) {
        float4 bv = ((const float4*)Bs)[d4];
        float4 o;
        o.x = (ca * acc[d4 * 4 + 0] + cb * bv.x) * inv;
        o.y = (ca * acc[d4 * 4 + 1] + cb * bv.y) * inv;
        o.z = (ca * acc[d4 * 4 + 2] + cb * bv.z) * inv;
        o.w = (ca * acc[d4 * 4 + 3] + cb * bv.w) * inv;
        hrow[d4] = o;
    }
}

// ---------------------------------------------------------------------------
// Kernel 2: edge scatter — 16 lanes per edge, one float4 red.global each
// edge_index is int32 (JAX x64 disabled: int64 request silently -> int32)
// ---------------------------------------------------------------------------
__global__ void __launch_bounds__(256)
scatter_kernel(const int* __restrict__ ei, float* __restrict__ out,
               int E, int N) {
    int idx = blockIdx.x * 256 + threadIdx.x;
    int e = idx >> 4;
    int l = idx & 15;
    if (e >= E) return;

    int s = __ldg(&ei[e]);
    int d = __ldg(&ei[(size_t)E + e]);
    // Guard: if dtype assumption is ever wrong this yields a rel_err signal,
    // not an illegal access.
    if ((unsigned)s >= (unsigned)N || (unsigned)d >= (unsigned)N) return;

    float4 v = __ldg((const float4*)(g_h + (size_t)s * 64) + l);
    float* dst = out + (size_t)d * 64 + l * 4;
    asm volatile("red.global.add.v4.f32 [%0], {%1, %2, %3, %4};"
                 :: "l"(dst), "f"(v.x), "f"(v.y), "f"(v.z), "f"(v.w)
                 : "memory");
    if (l == 0) {
        atomicAdd(&g_deg[d], 1.0f);
    }
}

// ---------------------------------------------------------------------------
// Kernel 3: finalize — mean + Poincare ball projection
// 16 lanes per node (half-warp), shuffle reduction for the squared norm.
// ---------------------------------------------------------------------------
__global__ void __launch_bounds__(256)
finalize_kernel(float* __restrict__ out, int N) {
    int idx = blockIdx.x * 256 + threadIdx.x;
    int n = idx >> 4;
    int l = idx & 15;
    if (n >= N) return;

    float dg  = fmaxf(g_deg[n], 1.0f);
    float inv = 1.0f / dg;

    float4* row = (float4*)(out + (size_t)n * 64);
    float4 v = row[l];
    v.x *= inv; v.y *= inv; v.z *= inv; v.w *= inv;

    float ss = v.x * v.x + v.y * v.y + v.z * v.z + v.w * v.w;
    unsigned mask = 0xFFFFu << (threadIdx.x & 16);  // the half-warp this lane is in
    ss += __shfl_xor_sync(mask, ss, 1);
    ss += __shfl_xor_sync(mask, ss, 2);
    ss += __shfl_xor_sync(mask, ss, 4);
    ss += __shfl_xor_sync(mask, ss, 8);

    float norm = fmaxf(sqrtf(ss), EPSF);
    if (norm > MAX_NORM) {
        float s = MAX_NORM / norm;
        v.x *= s; v.y *= s; v.z *= s; v.w *= s;
    }
    row[l] = v;
}

// ---------------------------------------------------------------------------
extern "C" void kernel_launch(void* const* d_in, const int* in_sizes, int n_in,
                              void* d_out, int out_size) {
    const float* x      = (const float*)d_in[0];
    const float* weight = (const float*)d_in[1];
    const float* bias   = (const float*)d_in[2];
    const int*   ei     = (const int*)d_in[3];   // int32 (JAX default x64 off)
    float*       out    = (float*)d_out;

    int N = in_sizes[0] / 64;
    int E = in_sizes[3] / 2;

    void* degp = nullptr;
    cudaGetSymbolAddress(&degp, g_deg);

    cudaMemsetAsync(out,  0, (size_t)N * 64 * sizeof(float));
    cudaMemsetAsync(degp, 0, (size_t)N * sizeof(float));

    prep_kernel<<<1, 64>>>(weight, bias);
    transform_kernel<<<(N + 255) / 256, 256>>>(x, N);

    long long sthreads = (long long)E * 16;
    scatter_kernel<<<(int)((sthreads + 255) / 256), 256>>>(ei, out, E, N);

    long long fthreads = (long long)N * 16;
    finalize_kernel<<<(int)((fthreads + 255) / 256), 256>>>(out, N);
}

// round 4
// speedup vs baseline: 1.8467x; 1.8467x over previous
#include <cuda_runtime.h>
#include <cstdint>

#define EPSF 1e-7f
#define MAX_NORM (1.0f - 1e-5f)
#define MAXN 100352        // capacity for N=100000 (multiple of 1024)
#define MAXE 1700000       // capacity for E=1600000
#define SCAN_BLK 1024

// Scratch (static device globals — no allocation allowed)
__device__ float g_h[(size_t)MAXN * 64];   // transformed node features
__device__ int   g_count[MAXN];            // in-degree
__device__ int   g_rowstart[MAXN];         // CSR row offsets (exclusive scan of count)
__device__ int   g_cursor[MAXN];           // fill cursors
__device__ int   g_csr[MAXE];              // CSR: src indices grouped by dst
__device__ int   g_blksum[MAXN / SCAN_BLK + 2];
__device__ float g_W[64 * 64];             // expmap0(weight)
__device__ float g_B[64];                  // expmap0(bias)
__device__ float g_By2;                    // ||expmap0(bias)||^2

// ---------------------------------------------------------------------------
// Kernel 0: tiny prep — expmap0 of weight rows and of bias
// ---------------------------------------------------------------------------
__global__ void prep_kernel(const float* __restrict__ weight,
                            const float* __restrict__ bias) {
    int i = threadIdx.x;
    if (i < 64) {
        float ss = 0.f;
        #pragma unroll
        for (int k = 0; k < 64; k++) { float w = weight[i * 64 + k]; ss += w * w; }
        float n = fmaxf(sqrtf(ss), EPSF);
        float s = tanhf(n) / n;
        #pragma unroll
        for (int k = 0; k < 64; k++) g_W[i * 64 + k] = weight[i * 64 + k] * s;
    }
    if (i == 0) {
        float ss = 0.f;
        #pragma unroll
        for (int k = 0; k < 64; k++) { float b = bias[k]; ss += b * b; }
        float n = fmaxf(sqrtf(ss), EPSF);
        float t = tanhf(n);
        float s = t / n;
        #pragma unroll
        for (int k = 0; k < 64; k++) g_B[k] = bias[k] * s;
        g_By2 = t * t;
    }
}

// ---------------------------------------------------------------------------
// Kernel 1: per-node hyperbolic transform (unchanged from R2; near roofline)
// ---------------------------------------------------------------------------
__global__ void __launch_bounds__(256)
transform_kernel(const float* __restrict__ x, int N) {
    __shared__ float Ws[64 * 64];
    __shared__ float Bs[64];
    int tid = threadIdx.x;
    for (int i = tid; i < 64 * 64; i += 256) Ws[i] = g_W[i];
    if (tid < 64) Bs[tid] = g_B[tid];
    __syncthreads();

    int n = blockIdx.x * 256 + tid;
    if (n >= N) return;

    const float4* xrow = (const float4*)(x + (size_t)n * 64);

    float acc[64];
    #pragma unroll
    for (int d = 0; d < 64; d++) acc[d] = 0.f;

    float xn2 = 0.f;
    for (int k4 = 0; k4 < 16; k4++) {
        float4 xk4 = __ldg(xrow + k4);
        xn2 += xk4.x * xk4.x + xk4.y * xk4.y + xk4.z * xk4.z + xk4.w * xk4.w;
        float xk[4] = {xk4.x, xk4.y, xk4.z, xk4.w};
        #pragma unroll
        for (int kk = 0; kk < 4; kk++) {
            int k = k4 * 4 + kk;
            const float4* wrow = (const float4*)&Ws[k * 64];
            float xv = xk[kk];
            #pragma unroll
            for (int d4 = 0; d4 < 16; d4++) {
                float4 w = wrow[d4];
                acc[d4 * 4 + 0] = fmaf(xv, w.x, acc[d4 * 4 + 0]);
                acc[d4 * 4 + 1] = fmaf(xv, w.y, acc[d4 * 4 + 1]);
                acc[d4 * 4 + 2] = fmaf(xv, w.z, acc[d4 * 4 + 2]);
                acc[d4 * 4 + 3] = fmaf(xv, w.w, acc[d4 * 4 + 3]);
            }
        }
    }

    float xn = fmaxf(sqrtf(xn2), EPSF);
    float Mxn2 = 0.f;
    #pragma unroll
    for (int d = 0; d < 64; d++) Mxn2 += acc[d] * acc[d];
    float Mxn = fmaxf(sqrtf(Mxn2), EPSF);

    float xc = fminf(xn, 1.0f - 1e-7f);
    float at = 0.5f * log1pf(2.0f * xc / (1.0f - xc));
    float t  = tanhf(Mxn / xn * at);
    float scale = t / Mxn;

    float x2 = t * t;                 // ||r|| = t exactly
    float xy = 0.f;
    #pragma unroll
    for (int d = 0; d < 64; d++) {
        acc[d] *= scale;
        xy = fmaf(acc[d], Bs[d], xy);
    }
    float y2  = g_By2;
    float ca  = 1.0f + 2.0f * xy + y2;
    float cb  = 1.0f - x2;
    float den = 1.0f + 2.0f * xy + x2 * y2;
    float inv = 1.0f / fmaxf(den, EPSF);

    float4* hrow = (float4*)(g_h + (size_t)n * 64);
    #pragma unroll
    for (int d4 = 0; d4 < 16; d4++) {
        float4 bv = ((const float4*)Bs)[d4];
        float4 o;
        o.x = (ca * acc[d4 * 4 + 0] + cb * bv.x) * inv;
        o.y = (ca * acc[d4 * 4 + 1] + cb * bv.y) * inv;
        o.z = (ca * acc[d4 * 4 + 2] + cb * bv.z) * inv;
        o.w = (ca * acc[d4 * 4 + 3] + cb * bv.w) * inv;
        hrow[d4] = o;
    }
}

// ---------------------------------------------------------------------------
// CSR build: histogram -> block scan -> top scan -> add offsets -> fill
// ---------------------------------------------------------------------------
__global__ void __launch_bounds__(256)
count_kernel(const int* __restrict__ ei, int E, int N) {
    int e = blockIdx.x * 256 + threadIdx.x;
    if (e >= E) return;
    int d = __ldg(&ei[(size_t)E + e]);
    if ((unsigned)d < (unsigned)N) atomicAdd(&g_count[d], 1);
}

// Exclusive scan of g_count within blocks of SCAN_BLK; block totals to g_blksum
__global__ void __launch_bounds__(SCAN_BLK)
scan_block_kernel(int Npad) {
    __shared__ int sh[SCAN_BLK];
    int gid = blockIdx.x * SCAN_BLK + threadIdx.x;
    int v = (gid < Npad) ? g_count[gid] : 0;
    sh[threadIdx.x] = v;
    __syncthreads();
    // Hillis-Steele inclusive scan
    int val = v;
    #pragma unroll
    for (int off = 1; off < SCAN_BLK; off <<= 1) {
        int add = (threadIdx.x >= off) ? sh[threadIdx.x - off] : 0;
        __syncthreads();
        val += add;
        sh[threadIdx.x] = val;
        __syncthreads();
    }
    if (gid < Npad) g_rowstart[gid] = val - v;   // exclusive
    if (threadIdx.x == SCAN_BLK - 1) g_blksum[blockIdx.x] = val;
}

__global__ void scan_top_kernel(int nblk) {
    // single block, <=128 sums — simple serial scan by thread 0 (nanoseconds)
    if (threadIdx.x == 0) {
        int run = 0;
        for (int b = 0; b < nblk; b++) {
            int s = g_blksum[b];
            g_blksum[b] = run;
            run += s;
        }
    }
}

__global__ void __launch_bounds__(256)
scan_add_kernel(int N) {
    int i = blockIdx.x * 256 + threadIdx.x;
    if (i >= N) return;
    int rs = g_rowstart[i] + g_blksum[i / SCAN_BLK];
    g_rowstart[i] = rs;
    g_cursor[i]   = rs;
}

__global__ void __launch_bounds__(256)
fill_kernel(const int* __restrict__ ei, int E, int N) {
    int e = blockIdx.x * 256 + threadIdx.x;
    if (e >= E) return;
    int s = __ldg(&ei[e]);
    int d = __ldg(&ei[(size_t)E + e]);
    if ((unsigned)s >= (unsigned)N || (unsigned)d >= (unsigned)N) return;
    int pos = atomicAdd(&g_cursor[d], 1);
    g_csr[pos] = s;
}

// ---------------------------------------------------------------------------
// Gather: 16 lanes per node, register accumulation, fused mean + projection.
// Unroll-by-4 over edges for MLP.
// ---------------------------------------------------------------------------
__global__ void __launch_bounds__(256)
gather_kernel(float* __restrict__ out, int N) {
    int idx = blockIdx.x * 256 + threadIdx.x;
    int n = idx >> 4;
    int l = idx & 15;
    if (n >= N) return;

    int start = g_rowstart[n];
    int cnt   = g_count[n];

    float4 acc = make_float4(0.f, 0.f, 0.f, 0.f);
    const int* lst = g_csr + start;

    int j = 0;
    for (; j + 4 <= cnt; j += 4) {
        int s0 = __ldg(&lst[j + 0]);
        int s1 = __ldg(&lst[j + 1]);
        int s2 = __ldg(&lst[j + 2]);
        int s3 = __ldg(&lst[j + 3]);
        float4 v0 = __ldg((const float4*)(g_h + (size_t)s0 * 64) + l);
        float4 v1 = __ldg((const float4*)(g_h + (size_t)s1 * 64) + l);
        float4 v2 = __ldg((const float4*)(g_h + (size_t)s2 * 64) + l);
        float4 v3 = __ldg((const float4*)(g_h + (size_t)s3 * 64) + l);
        acc.x += (v0.x + v1.x) + (v2.x + v3.x);
        acc.y += (v0.y + v1.y) + (v2.y + v3.y);
        acc.z += (v0.z + v1.z) + (v2.z + v3.z);
        acc.w += (v0.w + v1.w) + (v2.w + v3.w);
    }
    for (; j < cnt; j++) {
        int s0 = __ldg(&lst[j]);
        float4 v0 = __ldg((const float4*)(g_h + (size_t)s0 * 64) + l);
        acc.x += v0.x; acc.y += v0.y; acc.z += v0.z; acc.w += v0.w;
    }

    float inv = 1.0f / fmaxf((float)cnt, 1.0f);
    acc.x *= inv; acc.y *= inv; acc.z *= inv; acc.w *= inv;

    // ball projection: half-warp shuffle reduce of squared norm
    float ss = acc.x * acc.x + acc.y * acc.y + acc.z * acc.z + acc.w * acc.w;
    unsigned mask = 0xFFFFu << (threadIdx.x & 16);
    ss += __shfl_xor_sync(mask, ss, 1);
    ss += __shfl_xor_sync(mask, ss, 2);
    ss += __shfl_xor_sync(mask, ss, 4);
    ss += __shfl_xor_sync(mask, ss, 8);

    float norm = fmaxf(sqrtf(ss), EPSF);
    if (norm > MAX_NORM) {
        float sc = MAX_NORM / norm;
        acc.x *= sc; acc.y *= sc; acc.z *= sc; acc.w *= sc;
    }
    ((float4*)(out + (size_t)n * 64))[l] = acc;
}

// ---------------------------------------------------------------------------
extern "C" void kernel_launch(void* const* d_in, const int* in_sizes, int n_in,
                              void* d_out, int out_size) {
    const float* x      = (const float*)d_in[0];
    const float* weight = (const float*)d_in[1];
    const float* bias   = (const float*)d_in[2];
    const int*   ei     = (const int*)d_in[3];   // int32 (JAX x64 off)
    float*       out    = (float*)d_out;

    int N = in_sizes[0] / 64;
    int E = in_sizes[3] / 2;

    int Npad = ((N + SCAN_BLK - 1) / SCAN_BLK) * SCAN_BLK;
    int nblk = Npad / SCAN_BLK;

    void* cntp = nullptr;
    cudaGetSymbolAddress(&cntp, g_count);
    cudaMemsetAsync(cntp, 0, (size_t)Npad * sizeof(int));

    prep_kernel<<<1, 64>>>(weight, bias);
    count_kernel<<<(E + 255) / 256, 256>>>(ei, E, N);
    transform_kernel<<<(N + 255) / 256, 256>>>(x, N);
    scan_block_kernel<<<nblk, SCAN_BLK>>>(Npad);
    scan_top_kernel<<<1, 32>>>(nblk);
    scan_add_kernel<<<(N + 255) / 256, 256>>>(N);
    fill_kernel<<<(E + 255) / 256, 256>>>(ei, E, N);

    long long gthreads = (long long)N * 16;
    gather_kernel<<<(int)((gthreads + 255) / 256), 256>>>(out, N);
}

// round 5
// speedup vs baseline: 2.1297x; 1.1532x over previous
#include <cuda_runtime.h>
#include <cuda_fp16.h>
#include <cstdint>

#define EPSF 1e-7f
#define MAX_NORM (1.0f - 1e-5f)
#define MAXN 100352        // capacity for N=100000 (multiple of 1024)
#define MAXE 1700000       // capacity for E=1600000
#define SCAN_BLK 1024

// Scratch (static device globals — no allocation allowed)
__device__ __half g_h[(size_t)MAXN * 64];  // transformed node features (fp16)
__device__ int    g_count[MAXN];           // in-degree
__device__ int    g_rowstart[MAXN];        // CSR row offsets
__device__ int    g_cursor[MAXN];          // fill cursors
__device__ int    g_csr[MAXE];             // CSR: src indices grouped by dst
__device__ int    g_blksum[MAXN / SCAN_BLK + 2];

// ---------------------------------------------------------------------------
// Fused kernel: blocks [0,TB) = per-node hyperbolic transform (expmap0 of
// W/b computed in-block), blocks [TB,TB+CB) = degree histogram.
// The two phases are independent; fusing them overlaps compute with atomics.
// ---------------------------------------------------------------------------
__global__ void __launch_bounds__(256)
transform_count_kernel(const float* __restrict__ x,
                       const float* __restrict__ weight,
                       const float* __restrict__ bias,
                       const int* __restrict__ ei,
                       int N, int E, int TB) {
    int bid = blockIdx.x;
    int tid = threadIdx.x;

    if (bid >= TB) {
        // ---- degree histogram: 1024 edges per block, 4 per thread ----
        int base = (bid - TB) * 1024 + tid;
        #pragma unroll
        for (int k = 0; k < 4; k++) {
            int e = base + k * 256;
            if (e < E) {
                int d = __ldg(&ei[(size_t)E + e]);
                if ((unsigned)d < (unsigned)N) atomicAdd(&g_count[d], 1);
            }
        }
        return;
    }

    // ---- transform ----
    __shared__ float Ws[64 * 64];
    __shared__ float Bs[64];
    __shared__ float Ss[64];       // per-row scale for W
    __shared__ float sBy2, sBscale;

    // load raw weight coalesced
    for (int i = tid; i < 64 * 64; i += 256) Ws[i] = weight[i];
    if (tid < 64) Bs[tid] = bias[tid];
    __syncthreads();

    if (tid < 64) {                 // expmap0 scale per weight row
        float ss = 0.f;
        #pragma unroll
        for (int k = 0; k < 64; k++) { float w = Ws[tid * 64 + k]; ss += w * w; }
        float nw = fmaxf(sqrtf(ss), EPSF);
        Ss[tid] = tanhf(nw) / nw;
    }
    if (tid == 128) {               // expmap0 of bias (cheap serial, other warp)
        float ss = 0.f;
        #pragma unroll
        for (int k = 0; k < 64; k++) { float b = Bs[k]; ss += b * b; }
        float nb = fmaxf(sqrtf(ss), EPSF);
        float t = tanhf(nb);
        sBscale = t / nb;
        sBy2 = t * t;
    }
    __syncthreads();
    for (int i = tid; i < 64 * 64; i += 256) Ws[i] *= Ss[i >> 6];
    if (tid < 64) Bs[tid] *= sBscale;
    __syncthreads();

    int n = bid * 256 + tid;
    if (n >= N) return;

    const float4* xrow = (const float4*)(x + (size_t)n * 64);

    float acc[64];
    #pragma unroll
    for (int d = 0; d < 64; d++) acc[d] = 0.f;

    float xn2 = 0.f;
    for (int k4 = 0; k4 < 16; k4++) {
        float4 xk4 = __ldg(xrow + k4);
        xn2 += xk4.x * xk4.x + xk4.y * xk4.y + xk4.z * xk4.z + xk4.w * xk4.w;
        float xk[4] = {xk4.x, xk4.y, xk4.z, xk4.w};
        #pragma unroll
        for (int kk = 0; kk < 4; kk++) {
            int k = k4 * 4 + kk;
            const float4* wrow = (const float4*)&Ws[k * 64];
            float xv = xk[kk];
            #pragma unroll
            for (int d4 = 0; d4 < 16; d4++) {
                float4 w = wrow[d4];
                acc[d4 * 4 + 0] = fmaf(xv, w.x, acc[d4 * 4 + 0]);
                acc[d4 * 4 + 1] = fmaf(xv, w.y, acc[d4 * 4 + 1]);
                acc[d4 * 4 + 2] = fmaf(xv, w.z, acc[d4 * 4 + 2]);
                acc[d4 * 4 + 3] = fmaf(xv, w.w, acc[d4 * 4 + 3]);
            }
        }
    }

    float xn = fmaxf(sqrtf(xn2), EPSF);
    float Mxn2 = 0.f;
    #pragma unroll
    for (int d = 0; d < 64; d++) Mxn2 += acc[d] * acc[d];
    float Mxn = fmaxf(sqrtf(Mxn2), EPSF);

    float xc = fminf(xn, 1.0f - 1e-7f);
    float at = 0.5f * log1pf(2.0f * xc / (1.0f - xc));
    float t  = tanhf(Mxn / xn * at);
    float scale = t / Mxn;

    float x2 = t * t;              // ||r|| = tanh(.) exactly
    float xy = 0.f;
    #pragma unroll
    for (int d = 0; d < 64; d++) {
        acc[d] *= scale;
        xy = fmaf(acc[d], Bs[d], xy);
    }
    float y2  = sBy2;
    float ca  = 1.0f + 2.0f * xy + y2;
    float cb  = 1.0f - x2;
    float den = 1.0f + 2.0f * xy + x2 * y2;
    float inv = 1.0f / fmaxf(den, EPSF);

    // write h row as fp16 (8 x uint4 = 128B)
    uint4* hrow = (uint4*)(g_h + (size_t)n * 64);
    #pragma unroll
    for (int d8 = 0; d8 < 8; d8++) {
        float o[8];
        #pragma unroll
        for (int q = 0; q < 8; q++) {
            int d = d8 * 8 + q;
            o[q] = (ca * acc[d] + cb * Bs[d]) * inv;
        }
        uint4 u;
        __half2 h0 = __floats2half2_rn(o[0], o[1]);
        __half2 h1 = __floats2half2_rn(o[2], o[3]);
        __half2 h2 = __floats2half2_rn(o[4], o[5]);
        __half2 h3 = __floats2half2_rn(o[6], o[7]);
        u.x = *(unsigned*)&h0; u.y = *(unsigned*)&h1;
        u.z = *(unsigned*)&h2; u.w = *(unsigned*)&h3;
        hrow[d8] = u;
    }
}

// ---------------------------------------------------------------------------
// Scan: warp-shuffle two-level block scan + 128-thread top scan
// ---------------------------------------------------------------------------
__global__ void __launch_bounds__(SCAN_BLK)
scan_block_kernel(int Npad) {
    __shared__ int wsum[32];
    int tid = threadIdx.x, lane = tid & 31, w = tid >> 5;
    int gid = blockIdx.x * SCAN_BLK + tid;
    int v = (gid < Npad) ? g_count[gid] : 0;
    int val = v;
    #pragma unroll
    for (int off = 1; off < 32; off <<= 1) {
        int t = __shfl_up_sync(0xFFFFFFFFu, val, off);
        if (lane >= off) val += t;
    }
    if (lane == 31) wsum[w] = val;
    __syncthreads();
    if (w == 0) {
        int s = wsum[lane];
        #pragma unroll
        for (int off = 1; off < 32; off <<= 1) {
            int t = __shfl_up_sync(0xFFFFFFFFu, s, off);
            if (lane >= off) s += t;
        }
        wsum[lane] = s;
    }
    __syncthreads();
    int base = w ? wsum[w - 1] : 0;
    if (gid < Npad) g_rowstart[gid] = base + val - v;   // exclusive
    if (tid == 0) g_blksum[blockIdx.x] = wsum[31];
}

__global__ void __launch_bounds__(128)
scan_top_kernel(int nblk) {
    __shared__ int ws[4];
    int tid = threadIdx.x, lane = tid & 31, w = tid >> 5;
    int v = (tid < nblk) ? g_blksum[tid] : 0;
    int val = v;
    #pragma unroll
    for (int off = 1; off < 32; off <<= 1) {
        int t = __shfl_up_sync(0xFFFFFFFFu, val, off);
        if (lane >= off) val += t;
    }
    if (lane == 31) ws[w] = val;
    __syncthreads();
    if (tid == 0) {
        int run = 0;
        #pragma unroll
        for (int i = 0; i < 4; i++) { int s = ws[i]; ws[i] = run; run += s; }
    }
    __syncthreads();
    if (tid < nblk) g_blksum[tid] = ws[w] + val - v;    // exclusive
}

__global__ void __launch_bounds__(256)
scan_add_kernel(int N) {
    int i = blockIdx.x * 256 + threadIdx.x;
    if (i >= N) return;
    int rs = g_rowstart[i] + g_blksum[i / SCAN_BLK];
    g_rowstart[i] = rs;
    g_cursor[i]   = rs;
}

__global__ void __launch_bounds__(256)
fill_kernel(const int* __restrict__ ei, int E, int N) {
    int e = blockIdx.x * 256 + threadIdx.x;
    if (e >= E) return;
    int s = __ldg(&ei[e]);
    int d = __ldg(&ei[(size_t)E + e]);
    if ((unsigned)s >= (unsigned)N || (unsigned)d >= (unsigned)N) return;
    int pos = atomicAdd(&g_cursor[d], 1);
    g_csr[pos] = s;
}

// ---------------------------------------------------------------------------
// Gather: 8 lanes per node, fp16 rows (128B), register accumulation,
// fused mean + Poincare projection. Unroll-by-4 over edges for MLP.
// ---------------------------------------------------------------------------
__device__ __forceinline__ void acc8(float* a, uint4 u) {
    __half2 h0 = *(__half2*)&u.x, h1 = *(__half2*)&u.y;
    __half2 h2 = *(__half2*)&u.z, h3 = *(__half2*)&u.w;
    float2 f0 = __half22float2(h0), f1 = __half22float2(h1);
    float2 f2 = __half22float2(h2), f3 = __half22float2(h3);
    a[0] += f0.x; a[1] += f0.y; a[2] += f1.x; a[3] += f1.y;
    a[4] += f2.x; a[5] += f2.y; a[6] += f3.x; a[7] += f3.y;
}

__global__ void __launch_bounds__(256)
gather_kernel(float* __restrict__ out, int N) {
    int idx = blockIdx.x * 256 + threadIdx.x;
    int n = idx >> 3;
    int l = idx & 7;
    if (n >= N) return;

    int start = g_rowstart[n];
    int cnt   = g_count[n];

    float a[8];
    #pragma unroll
    for (int q = 0; q < 8; q++) a[q] = 0.f;

    const int* lst = g_csr + start;
    int j = 0;
    for (; j + 4 <= cnt; j += 4) {
        int s0 = __ldg(&lst[j + 0]);
        int s1 = __ldg(&lst[j + 1]);
        int s2 = __ldg(&lst[j + 2]);
        int s3 = __ldg(&lst[j + 3]);
        uint4 u0 = __ldg((const uint4*)(g_h + (size_t)s0 * 64) + l);
        uint4 u1 = __ldg((const uint4*)(g_h + (size_t)s1 * 64) + l);
        uint4 u2 = __ldg((const uint4*)(g_h + (size_t)s2 * 64) + l);
        uint4 u3 = __ldg((const uint4*)(g_h + (size_t)s3 * 64) + l);
        acc8(a, u0); acc8(a, u1); acc8(a, u2); acc8(a, u3);
    }
    for (; j < cnt; j++) {
        int s0 = __ldg(&lst[j]);
        uint4 u0 = __ldg((const uint4*)(g_h + (size_t)s0 * 64) + l);
        acc8(a, u0);
    }

    float inv = 1.0f / fmaxf((float)cnt, 1.0f);
    #pragma unroll
    for (int q = 0; q < 8; q++) a[q] *= inv;

    // squared-norm reduce across the 8-lane group
    float ss = 0.f;
    #pragma unroll
    for (int q = 0; q < 8; q++) ss = fmaf(a[q], a[q], ss);
    unsigned mask = 0xFFu << (threadIdx.x & 24);
    ss += __shfl_xor_sync(mask, ss, 1);
    ss += __shfl_xor_sync(mask, ss, 2);
    ss += __shfl_xor_sync(mask, ss, 4);

    float norm = fmaxf(sqrtf(ss), EPSF);
    if (norm > MAX_NORM) {
        float sc = MAX_NORM / norm;
        #pragma unroll
        for (int q = 0; q < 8; q++) a[q] *= sc;
    }
    float4* row = (float4*)(out + (size_t)n * 64 + l * 8);
    row[0] = make_float4(a[0], a[1], a[2], a[3]);
    row[1] = make_float4(a[4], a[5], a[6], a[7]);
}

// ---------------------------------------------------------------------------
extern "C" void kernel_launch(void* const* d_in, const int* in_sizes, int n_in,
                              void* d_out, int out_size) {
    const float* x      = (const float*)d_in[0];
    const float* weight = (const float*)d_in[1];
    const float* bias   = (const float*)d_in[2];
    const int*   ei     = (const int*)d_in[3];   // int32 (JAX x64 off)
    float*       out    = (float*)d_out;

    int N = in_sizes[0] / 64;
    int E = in_sizes[3] / 2;

    int Npad = ((N + SCAN_BLK - 1) / SCAN_BLK) * SCAN_BLK;
    int nblk = Npad / SCAN_BLK;

    void* cntp = nullptr;
    cudaGetSymbolAddress(&cntp, g_count);
    cudaMemsetAsync(cntp, 0, (size_t)Npad * sizeof(int));

    int TB = (N + 255) / 256;            // transform blocks
    int CB = (E + 1023) / 1024;          // count blocks (4 edges/thread)
    transform_count_kernel<<<TB + CB, 256>>>(x, weight, bias, ei, N, E, TB);

    scan_block_kernel<<<nblk, SCAN_BLK>>>(Npad);
    scan_top_kernel<<<1, 128>>>(nblk);
    scan_add_kernel<<<(N + 255) / 256, 256>>>(N);
    fill_kernel<<<(E + 255) / 256, 256>>>(ei, E, N);

    long long gthreads = (long long)N * 8;
    gather_kernel<<<(int)((gthreads + 255) / 256), 256>>>(out, N);
}